// round 14
// baseline (speedup 1.0000x reference)
#include <cuda_runtime.h>
#include <math.h>

#define NRES 512
#define CS 384
#define CZ 128
#define CH 16
#define NH 12
#define PQ 4
#define PV 8

// ---------------- f32x2 packed-math helpers (sm_103a) ----------------
__device__ __forceinline__ unsigned long long dup2(float v) {
    unsigned long long r;
    asm("mov.b64 %0, {%1, %1};" : "=l"(r) : "f"(v));
    return r;
}
__device__ __forceinline__ void fma2(unsigned long long& d, unsigned long long a,
                                     unsigned long long b) {
    asm("fma.rn.f32x2 %0, %1, %2, %0;" : "+l"(d) : "l"(a), "l"(b));
}
__device__ __forceinline__ float2 upk2(unsigned long long v) {
    float2 f;
    asm("mov.b64 {%0, %1}, %2;" : "=f"(f.x), "=f"(f.y) : "l"(v));
    return f;
}

// ---------------- device scratch ----------------
__device__ __align__(16) float g_proj[NRES * 1152];           // q|kv|qp|kvp
__device__ __align__(16) float g_v2[NRES * NH * 40];          // [j][h][v(16)|vpts(24)]
__device__ __align__(16) float g_A[NH * NRES * 32];           // logit lhs
__device__ __align__(16) float g_B[NH * NRES * 32];           // logit rhs
__device__ __align__(16) float g_pre[(size_t)NH * NRES * NRES]; // [h][i][j] pre-logits
__device__ __align__(16) float g_a[(size_t)NH * NRES * NRES];   // [h][i][j] softmaxed
__device__ __align__(16) float g_ovp[2 * NRES * 480];         // j-split partials
__device__ __align__(16) float g_cat[NRES * 2112];
__device__ __align__(16) float g_opart[4 * NRES * 384];

// =============== K1: tiled GEMM, g_proj[512x1152] = s @ [Wq|Wkv|Wqp|Wkvp] ===============
__global__ void k_gemm_proj(const float* __restrict__ s,
                            const float* __restrict__ Wq, const float* __restrict__ bq,
                            const float* __restrict__ Wkv, const float* __restrict__ bkv,
                            const float* __restrict__ Wqp, const float* __restrict__ bqp,
                            const float* __restrict__ Wkvp, const float* __restrict__ bkvp) {
    __shared__ float s_sh[64 * 36];
    __shared__ float w_sh[32 * 48];
    int tid = threadIdx.x;            // 192
    int tx = tid % 12, ty = tid / 12;
    int r0 = blockIdx.x * 64;
    int by = blockIdx.y;

    const float* W; const float* bv; int outw, coff, gc0;
    if (by < 4)       { W = Wq;   bv = bq;   outw = 192; coff = 48 * by;        gc0 = coff; }
    else if (by < 12) { W = Wkv;  bv = bkv;  outw = 384; coff = 48 * (by - 4);  gc0 = 192 + coff; }
    else if (by < 15) { W = Wqp;  bv = bqp;  outw = 144; coff = 48 * (by - 12); gc0 = 576 + coff; }
    else              { W = Wkvp; bv = bkvp; outw = 432; coff = 48 * (by - 15); gc0 = 720 + coff; }

    ulonglong2 acc2[4];
    #pragma unroll
    for (int r = 0; r < 4; r++) { acc2[r].x = 0ULL; acc2[r].y = 0ULL; }

    for (int kt = 0; kt < 12; kt++) {
        int k0 = kt * 32;
        for (int idx = tid; idx < 512; idx += 192) {
            int r = idx >> 3, c4 = (idx & 7) << 2;
            *(float4*)&s_sh[r * 36 + c4] = *(const float4*)&s[(r0 + r) * 384 + k0 + c4];
        }
        for (int idx = tid; idx < 384; idx += 192) {
            int k = idx / 12, c4 = (idx % 12) << 2;
            *(float4*)&w_sh[k * 48 + c4] = *(const float4*)&W[(k0 + k) * outw + coff + c4];
        }
        __syncthreads();
        #pragma unroll 8
        for (int k = 0; k < 32; k++) {
            ulonglong2 b2 = *(const ulonglong2*)&w_sh[k * 48 + tx * 4];
            unsigned long long a0 = dup2(s_sh[(ty * 4 + 0) * 36 + k]);
            unsigned long long a1 = dup2(s_sh[(ty * 4 + 1) * 36 + k]);
            unsigned long long a2 = dup2(s_sh[(ty * 4 + 2) * 36 + k]);
            unsigned long long a3 = dup2(s_sh[(ty * 4 + 3) * 36 + k]);
            fma2(acc2[0].x, a0, b2.x); fma2(acc2[0].y, a0, b2.y);
            fma2(acc2[1].x, a1, b2.x); fma2(acc2[1].y, a1, b2.y);
            fma2(acc2[2].x, a2, b2.x); fma2(acc2[2].y, a2, b2.y);
            fma2(acc2[3].x, a3, b2.x); fma2(acc2[3].y, a3, b2.y);
        }
        __syncthreads();
    }
    float4 bbv = *(const float4*)&bv[coff + tx * 4];
    #pragma unroll
    for (int r = 0; r < 4; r++) {
        float2 lo = upk2(acc2[r].x), hi = upk2(acc2[r].y);
        float4 o;
        o.x = lo.x + bbv.x; o.y = lo.y + bbv.y;
        o.z = hi.x + bbv.z; o.w = hi.y + bbv.w;
        *(float4*)&g_proj[(r0 + ty * 4 + r) * 1152 + gc0 + tx * 4] = o;
    }
}

// =============== K2: scatter + frame transform + build A/B logit factors ===============
__global__ void k_scatter(const float* __restrict__ rot, const float* __restrict__ trans,
                          const float* __restrict__ hwts) {
    int i = blockIdx.x;
    int tid = threadIdx.x;  // 192
    __shared__ float sp_q[144];  // h*12 + p*3 + d
    __shared__ float sp_k[144];
    __shared__ float s_hw[12], s_q2[12], s_k2[12];
    const float* pr = &g_proj[i * 1152];

    if (tid < 12) {
        float x = hwts[tid];
        float sp = (x > 20.f) ? x : log1pf(expf(x));
        s_hw[tid] = sp * 0.13608276348795434f;  // softplus * sqrt(1/54)
    }
    float R[9], T[3];
    #pragma unroll
    for (int d = 0; d < 9; d++) R[d] = rot[i * 9 + d];
    #pragma unroll
    for (int d = 0; d < 3; d++) T[d] = trans[i * 3 + d];
    if (tid < 48) {  // q points: tid = h*4+p
        float pl[3];
        #pragma unroll
        for (int d = 0; d < 3; d++) pl[d] = pr[576 + d * 48 + tid];
        #pragma unroll
        for (int d = 0; d < 3; d++)
            sp_q[tid * 3 + d] = R[d * 3 + 0] * pl[0] + R[d * 3 + 1] * pl[1] + R[d * 3 + 2] * pl[2] + T[d];
    } else {         // kv points: idx = h*12+pp
        int idx = tid - 48; int h = idx / 12, pp = idx % 12;
        float pl[3];
        #pragma unroll
        for (int d = 0; d < 3; d++) pl[d] = pr[720 + d * 144 + idx];
        #pragma unroll
        for (int d = 0; d < 3; d++) {
            float g = R[d * 3 + 0] * pl[0] + R[d * 3 + 1] * pl[1] + R[d * 3 + 2] * pl[2] + T[d];
            if (pp < 4) sp_k[h * 12 + pp * 3 + d] = g;
            else        g_v2[i * 480 + h * 40 + 16 + (pp - 4) * 3 + d] = g;
        }
    }
    // v channels
    {
        int h = tid >> 4, c = tid & 15;
        g_v2[i * 480 + h * 40 + c] = pr[192 + h * 32 + 16 + c];
    }
    __syncthreads();
    if (tid < 12) {
        float sq = 0.f, sk = 0.f;
        #pragma unroll
        for (int t = 0; t < 12; t++) {
            float a = sp_q[tid * 12 + t]; sq += a * a;
            float b = sp_k[tid * 12 + t]; sk += b * b;
        }
        s_q2[tid] = sq; s_k2[tid] = sk;
    }
    __syncthreads();
    const float C1 = 0.14433756729740643f;  // sqrt(1/48)
    {
        int h = tid >> 4, c = tid & 15;
        g_A[(h * NRES + i) * 32 + c] = C1 * pr[h * 16 + c];
        g_B[(h * NRES + i) * 32 + c] = pr[192 + h * 32 + c];
    }
    if (tid < 144) {
        int h = tid / 12, t = tid % 12;
        g_A[(h * NRES + i) * 32 + 16 + t] = s_hw[h] * sp_q[h * 12 + t];
        g_B[(h * NRES + i) * 32 + 16 + t] = sp_k[h * 12 + t];
    }
    if (tid < 12) {
        int h = tid; float hw = s_hw[h];
        float* A = &g_A[(h * NRES + i) * 32];
        float* B = &g_B[(h * NRES + i) * 32];
        A[28] = -0.5f * hw * s_q2[h];  B[28] = 1.f;
        A[29] = 1.f;                   B[29] = -0.5f * hw * s_k2[h];
        A[30] = 0.f;                   B[30] = 0.f;   // mask handled exactly in k_fused
        A[31] = 0.f;                   B[31] = 0.f;
    }
}

// =============== K3: pre-logit GEMM g_pre[h][i][j] = A[h,i,:32] . B[h,j,:32] ===============
__global__ void k_pre() {  // grid (8 it, 8 jt, 12 h), 256 threads
    __shared__ float a_t[64 * 33];
    __shared__ float b_t[64 * 33];
    int h = blockIdx.z;
    int i0 = blockIdx.x * 64, j0 = blockIdx.y * 64;
    int tid = threadIdx.x;
    for (int f = tid; f < 512; f += 256) {
        int r = f >> 3, k4 = (f & 7) << 2;
        float4 v = *(const float4*)&g_A[(h * NRES + i0 + r) * 32 + k4];
        a_t[r * 33 + k4] = v.x; a_t[r * 33 + k4 + 1] = v.y;
        a_t[r * 33 + k4 + 2] = v.z; a_t[r * 33 + k4 + 3] = v.w;
        float4 w = *(const float4*)&g_B[(h * NRES + j0 + r) * 32 + k4];
        b_t[r * 33 + k4] = w.x; b_t[r * 33 + k4 + 1] = w.y;
        b_t[r * 33 + k4 + 2] = w.z; b_t[r * 33 + k4 + 3] = w.w;
    }
    __syncthreads();
    int tx = tid & 15, ty = tid >> 4;
    float acc[4][4];
    #pragma unroll
    for (int r = 0; r < 4; r++)
        #pragma unroll
        for (int u = 0; u < 4; u++) acc[r][u] = 0.f;
    #pragma unroll 8
    for (int k = 0; k < 32; k++) {
        float av[4], bv[4];
        #pragma unroll
        for (int r = 0; r < 4; r++) av[r] = a_t[(ty * 4 + r) * 33 + k];
        #pragma unroll
        for (int u = 0; u < 4; u++) bv[u] = b_t[(tx * 4 + u) * 33 + k];
        #pragma unroll
        for (int r = 0; r < 4; r++)
            #pragma unroll
            for (int u = 0; u < 4; u++) acc[r][u] += av[r] * bv[u];
    }
    #pragma unroll
    for (int r = 0; r < 4; r++) {
        float4 o = make_float4(acc[r][0], acc[r][1], acc[r][2], acc[r][3]);
        *(float4*)&g_pre[((size_t)h * NRES + i0 + ty * 4 + r) * NRES + j0 + tx * 4] = o;
    }
}

// =============== K4: fused bias + logits + softmax + o_pair, per residue i ===============
// smem: zc[128*132]=16896  av2[512*12]=6144  wbT[12*128]=1536  -> 24576 floats = 98304 B
// (phase D reduction dred[12*512]=6144 overlays the zc region only)
__global__ __launch_bounds__(512) void k_fused(const float* __restrict__ z,
                                               const float* __restrict__ Wb,
                                               const float* __restrict__ bb,
                                               const float* __restrict__ mask) {
    extern __shared__ float sm[];
    float* zc  = sm;            // one 128-row j-chunk of z (132 stride pad)
    float* av2 = sm + 16896;    // [j][12]
    float* wbT = sm + 23040;    // [h][128]
    float* dred = sm;           // [h][jsub(4)][128] overlay (zc region, av2 untouched)
    int i = blockIdx.x;
    int tid = threadIdx.x;      // 512
    int lane = tid & 31, wid = tid >> 5;

    for (int idx = tid; idx < 1536; idx += 512) {
        int h = idx >> 7, k = idx & 127;
        wbT[idx] = Wb[k * 12 + h];
    }

    // ---- phase A: av2[j][h] = z[i,j,:] . Wb[:,h]  (chunk-gated; 4 warps/SMSP-balanced)
    int my_chunk = tid >> 7;
    int jloc_a = tid & 127;
    for (int chunk = 0; chunk < 4; chunk++) {
        __syncthreads();
        for (int f = tid; f < 4096; f += 512) {
            int r = f >> 5, c4 = (f & 31) << 2;
            *(float4*)&zc[r * 132 + c4] =
                *(const float4*)&z[((size_t)(i * NRES) + chunk * 128 + r) * CZ + c4];
        }
        __syncthreads();
        if (my_chunk == chunk) {
            unsigned long long acc2[12];
            #pragma unroll
            for (int h = 0; h < 12; h++) acc2[h] = 0ULL;
            #pragma unroll 4
            for (int c4 = 0; c4 < 32; c4++) {
                ulonglong2 zv = *(const ulonglong2*)&zc[jloc_a * 132 + c4 * 4];
                #pragma unroll
                for (int h = 0; h < 12; h++) {
                    ulonglong2 wv = *(const ulonglong2*)&wbT[h * 128 + c4 * 4];
                    fma2(acc2[h], zv.x, wv.x);
                    fma2(acc2[h], zv.y, wv.y);
                }
            }
            int j = chunk * 128 + jloc_a;
            #pragma unroll
            for (int h = 0; h < 12; h++) {
                float2 p = upk2(acc2[h]);
                av2[j * 12 + h] = p.x + p.y;
            }
        }
    }
    __syncthreads();

    // ---- phase B: full logits (exact mask term) ----
    {
        int j = tid;
        float mterm = 100000.0f * (mask[i] * mask[j] - 1.0f);
        const float C2 = 0.5773502691896258f;  // sqrt(1/3)
        #pragma unroll
        for (int h = 0; h < 12; h++) {
            float lg = g_pre[((size_t)h * NRES + i) * NRES + j] +
                       C2 * (av2[j * 12 + h] + bb[h]) + mterm;
            av2[j * 12 + h] = lg;
        }
    }
    __syncthreads();

    // ---- phase C: softmax, one warp per head ----
    if (wid < 12) {
        int h = wid;
        float vals[16];
        float m = -3.4e38f;
        #pragma unroll
        for (int u = 0; u < 16; u++) {
            vals[u] = av2[(u * 32 + lane) * 12 + h];
            m = fmaxf(m, vals[u]);
        }
        #pragma unroll
        for (int off = 16; off > 0; off >>= 1) m = fmaxf(m, __shfl_xor_sync(0xffffffffu, m, off));
        float s = 0.f;
        #pragma unroll
        for (int u = 0; u < 16; u++) { vals[u] = __expf(vals[u] - m); s += vals[u]; }
        #pragma unroll
        for (int off = 16; off > 0; off >>= 1) s += __shfl_xor_sync(0xffffffffu, s, off);
        float inv = 1.0f / s;
        #pragma unroll
        for (int u = 0; u < 16; u++) {
            float an = vals[u] * inv;
            av2[(u * 32 + lane) * 12 + h] = an;
            g_a[((size_t)h * NRES + i) * NRES + u * 32 + lane] = an;
        }
    }
    __syncthreads();

    // ---- phase D: o_pair[h][c] = sum_j a[j][h] * z[i,j,c]  (head-pair packing) ----
    // thread = (channel c = tid&127, jsub = tid>>7 -> 32 rows/chunk)
    // a loads are broadcast LDS.128 (pair-contiguous in h); only z needs dup2.
    int c = tid & 127;
    int jsub = tid >> 7;   // 0..3
    unsigned long long pacc[6];
    #pragma unroll
    for (int p = 0; p < 6; p++) pacc[p] = 0ULL;
    for (int chunk = 0; chunk < 4; chunk++) {
        __syncthreads();
        for (int f = tid; f < 4096; f += 512) {
            int r = f >> 5, c4 = (f & 31) << 2;
            *(float4*)&zc[r * 132 + c4] =
                *(const float4*)&z[((size_t)(i * NRES) + chunk * 128 + r) * CZ + c4];
        }
        __syncthreads();
        #pragma unroll 4
        for (int jj = 0; jj < 32; jj++) {
            int jloc = jsub * 32 + jj;
            int j = chunk * 128 + jloc;
            unsigned long long zs = dup2(zc[jloc * 132 + c]);
            ulonglong2 u0 = *(const ulonglong2*)&av2[j * 12];      // h 0-3
            ulonglong2 u1 = *(const ulonglong2*)&av2[j * 12 + 4];  // h 4-7
            ulonglong2 u2 = *(const ulonglong2*)&av2[j * 12 + 8];  // h 8-11
            fma2(pacc[0], zs, u0.x); fma2(pacc[1], zs, u0.y);
            fma2(pacc[2], zs, u1.x); fma2(pacc[3], zs, u1.y);
            fma2(pacc[4], zs, u2.x); fma2(pacc[5], zs, u2.y);
        }
    }
    // reduce 4 jsub partials per (h, channel): dred[h*512 + jsub*128 + c]
    __syncthreads();
    #pragma unroll
    for (int p = 0; p < 6; p++) {
        float2 pr = upk2(pacc[p]);
        dred[(2 * p + 0) * 512 + jsub * 128 + c] = pr.x;
        dred[(2 * p + 1) * 512 + jsub * 128 + c] = pr.y;
    }
    __syncthreads();
    #pragma unroll
    for (int r = 0; r < 3; r++) {
        int idx = tid + 512 * r;     // 0..1535
        int h = idx >> 7, cc = idx & 127;
        float ssum = 0.f;
        #pragma unroll
        for (int js = 0; js < 4; js++) ssum += dred[h * 512 + js * 128 + cc];
        g_cat[i * 2112 + 576 + h * 128 + cc] = ssum;
    }
}

// =============== K5: o + o_pt GEMM, j-split partials ===============
// grid (16 i-tiles of 32, 12 h, 2 j-splits), 320 threads
__global__ void k_ov() {
    extern __shared__ float sm[];
    float* a_t  = sm;          // 32 * 260
    float* v2_t = sm + 8320;   // 256 * 40
    int i0 = blockIdx.x * 32;
    int h = blockIdx.y;
    int j0 = blockIdx.z * 256;
    int tid = threadIdx.x;
    for (int f = tid; f < 2048; f += 320) {
        int r = f >> 6, j4 = (f & 63) << 2;
        *(float4*)&a_t[r * 260 + j4] =
            *(const float4*)&g_a[((size_t)h * NRES + i0 + r) * NRES + j0 + j4];
    }
    for (int f = tid; f < 2560; f += 320) {
        int jj = f / 10, c4 = (f % 10) << 2;
        *(float4*)&v2_t[jj * 40 + c4] = *(const float4*)&g_v2[(j0 + jj) * 480 + h * 40 + c4];
    }
    __syncthreads();
    int row = tid & 31, cg = tid >> 5;  // cg 0..9
    ulonglong2 acc2; acc2.x = 0ULL; acc2.y = 0ULL;
    #pragma unroll 4
    for (int j4 = 0; j4 < 64; j4++) {
        float4 a4 = *(const float4*)&a_t[row * 260 + j4 * 4];
        ulonglong2 v0 = *(const ulonglong2*)&v2_t[(j4 * 4 + 0) * 40 + cg * 4];
        ulonglong2 v1 = *(const ulonglong2*)&v2_t[(j4 * 4 + 1) * 40 + cg * 4];
        ulonglong2 v2 = *(const ulonglong2*)&v2_t[(j4 * 4 + 2) * 40 + cg * 4];
        ulonglong2 v3 = *(const ulonglong2*)&v2_t[(j4 * 4 + 3) * 40 + cg * 4];
        unsigned long long d0 = dup2(a4.x), d1 = dup2(a4.y), d2 = dup2(a4.z), d3 = dup2(a4.w);
        fma2(acc2.x, d0, v0.x); fma2(acc2.y, d0, v0.y);
        fma2(acc2.x, d1, v1.x); fma2(acc2.y, d1, v1.y);
        fma2(acc2.x, d2, v2.x); fma2(acc2.y, d2, v2.y);
        fma2(acc2.x, d3, v3.x); fma2(acc2.y, d3, v3.y);
    }
    float2 lo = upk2(acc2.x), hi = upk2(acc2.y);
    float4 o = make_float4(lo.x, lo.y, hi.x, hi.y);
    *(float4*)&g_ovp[((size_t)blockIdx.z * NRES + i0 + row) * 480 + h * 40 + cg * 4] = o;
}

// =============== K6: reduce j-split partials + inverse frame + norms ===============
__global__ void k_ovred(const float* __restrict__ rot, const float* __restrict__ trans) {
    int i = blockIdx.x;
    int tid = threadIdx.x;  // 192
    {
        int h = tid >> 4, c = tid & 15;
        float v = g_ovp[(size_t)i * 480 + h * 40 + c] +
                  g_ovp[(size_t)(NRES + i) * 480 + h * 40 + c];
        g_cat[i * 2112 + tid] = v;
    }
    if (tid < 96) {
        int h = tid >> 3, p = tid & 7;
        float s0 = g_ovp[(size_t)i * 480 + h * 40 + 16 + p * 3 + 0] +
                   g_ovp[(size_t)(NRES + i) * 480 + h * 40 + 16 + p * 3 + 0];
        float s1 = g_ovp[(size_t)i * 480 + h * 40 + 16 + p * 3 + 1] +
                   g_ovp[(size_t)(NRES + i) * 480 + h * 40 + 16 + p * 3 + 1];
        float s2 = g_ovp[(size_t)i * 480 + h * 40 + 16 + p * 3 + 2] +
                   g_ovp[(size_t)(NRES + i) * 480 + h * 40 + 16 + p * 3 + 2];
        float g0 = s0 - trans[i * 3 + 0];
        float g1 = s1 - trans[i * 3 + 1];
        float g2 = s2 - trans[i * 3 + 2];
        float lx = rot[i * 9 + 0] * g0 + rot[i * 9 + 3] * g1 + rot[i * 9 + 6] * g2;
        float ly = rot[i * 9 + 1] * g0 + rot[i * 9 + 4] * g1 + rot[i * 9 + 7] * g2;
        float lz = rot[i * 9 + 2] * g0 + rot[i * 9 + 5] * g1 + rot[i * 9 + 8] * g2;
        float nrm = sqrtf(lx * lx + ly * ly + lz * lz + 1e-8f);
        g_cat[i * 2112 + 192 + tid] = lx;
        g_cat[i * 2112 + 288 + tid] = ly;
        g_cat[i * 2112 + 384 + tid] = lz;
        g_cat[i * 2112 + 480 + tid] = nrm;
    }
}

// =============== K7: split-K output GEMM (64x48 tiles, 4x4 micro, f32x2) ===============
__global__ void k_out(const float* __restrict__ Wout) {
    __shared__ float cat_s[64 * 48];
    __shared__ float w_s[48 * 48];
    int tid = threadIdx.x;             // 192
    int tx = tid % 12, ty = tid / 12;
    int i0 = blockIdx.x * 64;
    int c0 = blockIdx.y * 48;
    int ks = blockIdx.z;
    ulonglong2 acc2[4];
    #pragma unroll
    for (int r = 0; r < 4; r++) { acc2[r].x = 0ULL; acc2[r].y = 0ULL; }

    for (int kc = 0; kc < 11; kc++) {
        int k0 = ks * 528 + kc * 48;
        __syncthreads();
        for (int f = tid; f < 768; f += 192) {
            int r = f / 12, c4 = (f % 12) << 2;
            *(float4*)&cat_s[r * 48 + c4] = *(const float4*)&g_cat[(i0 + r) * 2112 + k0 + c4];
        }
        for (int f = tid; f < 576; f += 192) {
            int r = f / 12, c4 = (f % 12) << 2;
            *(float4*)&w_s[r * 48 + c4] = *(const float4*)&Wout[(k0 + r) * 384 + c0 + c4];
        }
        __syncthreads();
        #pragma unroll 8
        for (int k = 0; k < 48; k++) {
            ulonglong2 wv = *(const ulonglong2*)&w_s[k * 48 + tx * 4];
            unsigned long long a0 = dup2(cat_s[(ty * 4 + 0) * 48 + k]);
            unsigned long long a1 = dup2(cat_s[(ty * 4 + 1) * 48 + k]);
            unsigned long long a2 = dup2(cat_s[(ty * 4 + 2) * 48 + k]);
            unsigned long long a3 = dup2(cat_s[(ty * 4 + 3) * 48 + k]);
            fma2(acc2[0].x, a0, wv.x); fma2(acc2[0].y, a0, wv.y);
            fma2(acc2[1].x, a1, wv.x); fma2(acc2[1].y, a1, wv.y);
            fma2(acc2[2].x, a2, wv.x); fma2(acc2[2].y, a2, wv.y);
            fma2(acc2[3].x, a3, wv.x); fma2(acc2[3].y, a3, wv.y);
        }
    }
    #pragma unroll
    for (int r = 0; r < 4; r++) {
        float2 lo = upk2(acc2[r].x), hi = upk2(acc2[r].y);
        float4 o = make_float4(lo.x, lo.y, hi.x, hi.y);
        *(float4*)&g_opart[((size_t)ks * NRES + i0 + ty * 4 + r) * 384 + c0 + tx * 4] = o;
    }
}

__global__ void k_out_red(const float* __restrict__ bout, float* __restrict__ out) {
    int f = blockIdx.x * 256 + threadIdx.x;  // 49152 float4 jobs
    int i = f / 96;
    int c4 = (f % 96) * 4;
    float4 s0 = *(const float4*)&g_opart[(size_t)0 * 196608 + i * 384 + c4];
    float4 s1 = *(const float4*)&g_opart[(size_t)1 * 196608 + i * 384 + c4];
    float4 s2 = *(const float4*)&g_opart[(size_t)2 * 196608 + i * 384 + c4];
    float4 s3 = *(const float4*)&g_opart[(size_t)3 * 196608 + i * 384 + c4];
    float4 bv = *(const float4*)&bout[c4];
    float4 o;
    o.x = s0.x + s1.x + s2.x + s3.x + bv.x;
    o.y = s0.y + s1.y + s2.y + s3.y + bv.y;
    o.z = s0.z + s1.z + s2.z + s3.z + bv.z;
    o.w = s0.w + s1.w + s2.w + s3.w + bv.w;
    *(float4*)&out[i * 384 + c4] = o;
}

extern "C" void kernel_launch(void* const* d_in, const int* in_sizes, int n_in,
                              void* d_out, int out_size) {
    const float* s     = (const float*)d_in[0];
    const float* z     = (const float*)d_in[1];
    const float* rot   = (const float*)d_in[2];
    const float* trans = (const float*)d_in[3];
    const float* mask  = (const float*)d_in[4];
    const float* Wq    = (const float*)d_in[5];
    const float* bq    = (const float*)d_in[6];
    const float* Wkv   = (const float*)d_in[7];
    const float* bkv   = (const float*)d_in[8];
    const float* Wqp   = (const float*)d_in[9];
    const float* bqp   = (const float*)d_in[10];
    const float* Wkvp  = (const float*)d_in[11];
    const float* bkvp  = (const float*)d_in[12];
    const float* Wb    = (const float*)d_in[13];
    const float* bb    = (const float*)d_in[14];
    const float* hwts  = (const float*)d_in[15];
    const float* Wout  = (const float*)d_in[16];
    const float* bout  = (const float*)d_in[17];
    float* out = (float*)d_out;

    const int FUSED_SMEM = 24576 * 4;   // 98304 B
    const int OV_SMEM    = 18560 * 4;   // 74240 B
    cudaFuncSetAttribute(k_fused, cudaFuncAttributeMaxDynamicSharedMemorySize, FUSED_SMEM);
    cudaFuncSetAttribute(k_ov, cudaFuncAttributeMaxDynamicSharedMemorySize, OV_SMEM);

    k_gemm_proj<<<dim3(8, 24), 192>>>(s, Wq, bq, Wkv, bkv, Wqp, bqp, Wkvp, bkvp);
    k_scatter<<<NRES, 192>>>(rot, trans, hwts);
    k_pre<<<dim3(8, 8, 12), 256>>>();
    k_fused<<<NRES, 512, FUSED_SMEM>>>(z, Wb, bb, mask);
    k_ov<<<dim3(16, 12, 2), 320, OV_SMEM>>>();
    k_ovred<<<NRES, 192>>>(rot, trans);
    k_out<<<dim3(8, 8, 4), 192>>>(Wout);
    k_out_red<<<192, 256>>>(bout, out);
}

// round 15
// speedup vs baseline: 1.0635x; 1.0635x over previous
#include <cuda_runtime.h>
#include <math.h>

#define NRES 512
#define CS 384
#define CZ 128
#define CH 16
#define NH 12
#define PQ 4
#define PV 8

// ---------------- f32x2 packed-math helpers (sm_103a) ----------------
__device__ __forceinline__ unsigned long long dup2(float v) {
    unsigned long long r;
    asm("mov.b64 %0, {%1, %1};" : "=l"(r) : "f"(v));
    return r;
}
__device__ __forceinline__ void fma2(unsigned long long& d, unsigned long long a,
                                     unsigned long long b) {
    asm("fma.rn.f32x2 %0, %1, %2, %0;" : "+l"(d) : "l"(a), "l"(b));
}
__device__ __forceinline__ float2 upk2(unsigned long long v) {
    float2 f;
    asm("mov.b64 {%0, %1}, %2;" : "=f"(f.x), "=f"(f.y) : "l"(v));
    return f;
}

// ---------------- device scratch ----------------
__device__ __align__(16) float g_proj[NRES * 1152];           // q|kv|qp|kvp
__device__ __align__(16) float g_v2[NRES * NH * 40];          // [j][h][v(16)|vpts(24)]
__device__ __align__(16) float g_A[NH * NRES * 32];           // logit lhs
__device__ __align__(16) float g_B[NH * NRES * 32];           // logit rhs
__device__ __align__(16) float g_pre[(size_t)NH * NRES * NRES]; // [h][i][j] pre-logits
__device__ __align__(16) float g_a[(size_t)NH * NRES * NRES];   // [h][i][j] softmaxed
__device__ __align__(16) float g_ovp[2 * NRES * 480];         // j-split partials
__device__ __align__(16) float g_cat[NRES * 2112];
__device__ __align__(16) float g_opart[4 * NRES * 384];

// =============== K1: tiled GEMM, g_proj[512x1152] = s @ [Wq|Wkv|Wqp|Wkvp] ===============
__global__ void k_gemm_proj(const float* __restrict__ s,
                            const float* __restrict__ Wq, const float* __restrict__ bq,
                            const float* __restrict__ Wkv, const float* __restrict__ bkv,
                            const float* __restrict__ Wqp, const float* __restrict__ bqp,
                            const float* __restrict__ Wkvp, const float* __restrict__ bkvp) {
    __shared__ float s_sh[64 * 36];
    __shared__ float w_sh[32 * 48];
    int tid = threadIdx.x;            // 192
    int tx = tid % 12, ty = tid / 12;
    int r0 = blockIdx.x * 64;
    int by = blockIdx.y;

    const float* W; const float* bv; int outw, coff, gc0;
    if (by < 4)       { W = Wq;   bv = bq;   outw = 192; coff = 48 * by;        gc0 = coff; }
    else if (by < 12) { W = Wkv;  bv = bkv;  outw = 384; coff = 48 * (by - 4);  gc0 = 192 + coff; }
    else if (by < 15) { W = Wqp;  bv = bqp;  outw = 144; coff = 48 * (by - 12); gc0 = 576 + coff; }
    else              { W = Wkvp; bv = bkvp; outw = 432; coff = 48 * (by - 15); gc0 = 720 + coff; }

    ulonglong2 acc2[4];
    #pragma unroll
    for (int r = 0; r < 4; r++) { acc2[r].x = 0ULL; acc2[r].y = 0ULL; }

    for (int kt = 0; kt < 12; kt++) {
        int k0 = kt * 32;
        for (int idx = tid; idx < 512; idx += 192) {
            int r = idx >> 3, c4 = (idx & 7) << 2;
            *(float4*)&s_sh[r * 36 + c4] = *(const float4*)&s[(r0 + r) * 384 + k0 + c4];
        }
        for (int idx = tid; idx < 384; idx += 192) {
            int k = idx / 12, c4 = (idx % 12) << 2;
            *(float4*)&w_sh[k * 48 + c4] = *(const float4*)&W[(k0 + k) * outw + coff + c4];
        }
        __syncthreads();
        #pragma unroll 8
        for (int k = 0; k < 32; k++) {
            ulonglong2 b2 = *(const ulonglong2*)&w_sh[k * 48 + tx * 4];
            unsigned long long a0 = dup2(s_sh[(ty * 4 + 0) * 36 + k]);
            unsigned long long a1 = dup2(s_sh[(ty * 4 + 1) * 36 + k]);
            unsigned long long a2 = dup2(s_sh[(ty * 4 + 2) * 36 + k]);
            unsigned long long a3 = dup2(s_sh[(ty * 4 + 3) * 36 + k]);
            fma2(acc2[0].x, a0, b2.x); fma2(acc2[0].y, a0, b2.y);
            fma2(acc2[1].x, a1, b2.x); fma2(acc2[1].y, a1, b2.y);
            fma2(acc2[2].x, a2, b2.x); fma2(acc2[2].y, a2, b2.y);
            fma2(acc2[3].x, a3, b2.x); fma2(acc2[3].y, a3, b2.y);
        }
        __syncthreads();
    }
    float4 bbv = *(const float4*)&bv[coff + tx * 4];
    #pragma unroll
    for (int r = 0; r < 4; r++) {
        float2 lo = upk2(acc2[r].x), hi = upk2(acc2[r].y);
        float4 o;
        o.x = lo.x + bbv.x; o.y = lo.y + bbv.y;
        o.z = hi.x + bbv.z; o.w = hi.y + bbv.w;
        *(float4*)&g_proj[(r0 + ty * 4 + r) * 1152 + gc0 + tx * 4] = o;
    }
}

// =============== K2: scatter + frame transform + build A/B logit factors ===============
__global__ void k_scatter(const float* __restrict__ rot, const float* __restrict__ trans,
                          const float* __restrict__ hwts) {
    int i = blockIdx.x;
    int tid = threadIdx.x;  // 192
    __shared__ float sp_q[144];  // h*12 + p*3 + d
    __shared__ float sp_k[144];
    __shared__ float s_hw[12], s_q2[12], s_k2[12];
    const float* pr = &g_proj[i * 1152];

    if (tid < 12) {
        float x = hwts[tid];
        float sp = (x > 20.f) ? x : log1pf(expf(x));
        s_hw[tid] = sp * 0.13608276348795434f;  // softplus * sqrt(1/54)
    }
    float R[9], T[3];
    #pragma unroll
    for (int d = 0; d < 9; d++) R[d] = rot[i * 9 + d];
    #pragma unroll
    for (int d = 0; d < 3; d++) T[d] = trans[i * 3 + d];
    if (tid < 48) {  // q points: tid = h*4+p
        float pl[3];
        #pragma unroll
        for (int d = 0; d < 3; d++) pl[d] = pr[576 + d * 48 + tid];
        #pragma unroll
        for (int d = 0; d < 3; d++)
            sp_q[tid * 3 + d] = R[d * 3 + 0] * pl[0] + R[d * 3 + 1] * pl[1] + R[d * 3 + 2] * pl[2] + T[d];
    } else {         // kv points: idx = h*12+pp
        int idx = tid - 48; int h = idx / 12, pp = idx % 12;
        float pl[3];
        #pragma unroll
        for (int d = 0; d < 3; d++) pl[d] = pr[720 + d * 144 + idx];
        #pragma unroll
        for (int d = 0; d < 3; d++) {
            float g = R[d * 3 + 0] * pl[0] + R[d * 3 + 1] * pl[1] + R[d * 3 + 2] * pl[2] + T[d];
            if (pp < 4) sp_k[h * 12 + pp * 3 + d] = g;
            else        g_v2[i * 480 + h * 40 + 16 + (pp - 4) * 3 + d] = g;
        }
    }
    // v channels
    {
        int h = tid >> 4, c = tid & 15;
        g_v2[i * 480 + h * 40 + c] = pr[192 + h * 32 + 16 + c];
    }
    __syncthreads();
    if (tid < 12) {
        float sq = 0.f, sk = 0.f;
        #pragma unroll
        for (int t = 0; t < 12; t++) {
            float a = sp_q[tid * 12 + t]; sq += a * a;
            float b = sp_k[tid * 12 + t]; sk += b * b;
        }
        s_q2[tid] = sq; s_k2[tid] = sk;
    }
    __syncthreads();
    const float C1 = 0.14433756729740643f;  // sqrt(1/48)
    {
        int h = tid >> 4, c = tid & 15;
        g_A[(h * NRES + i) * 32 + c] = C1 * pr[h * 16 + c];
        g_B[(h * NRES + i) * 32 + c] = pr[192 + h * 32 + c];
    }
    if (tid < 144) {
        int h = tid / 12, t = tid % 12;
        g_A[(h * NRES + i) * 32 + 16 + t] = s_hw[h] * sp_q[h * 12 + t];
        g_B[(h * NRES + i) * 32 + 16 + t] = sp_k[h * 12 + t];
    }
    if (tid < 12) {
        int h = tid; float hw = s_hw[h];
        float* A = &g_A[(h * NRES + i) * 32];
        float* B = &g_B[(h * NRES + i) * 32];
        A[28] = -0.5f * hw * s_q2[h];  B[28] = 1.f;
        A[29] = 1.f;                   B[29] = -0.5f * hw * s_k2[h];
        A[30] = 0.f;                   B[30] = 0.f;   // mask handled exactly in k_fused
        A[31] = 0.f;                   B[31] = 0.f;
    }
}

// =============== K3: pre-logit GEMM g_pre[h][i][j] = A[h,i,:32] . B[h,j,:32] ===============
__global__ void k_pre() {  // grid (8 it, 8 jt, 12 h), 256 threads
    __shared__ float a_t[64 * 33];
    __shared__ float b_t[64 * 33];
    int h = blockIdx.z;
    int i0 = blockIdx.x * 64, j0 = blockIdx.y * 64;
    int tid = threadIdx.x;
    for (int f = tid; f < 512; f += 256) {
        int r = f >> 3, k4 = (f & 7) << 2;
        float4 v = *(const float4*)&g_A[(h * NRES + i0 + r) * 32 + k4];
        a_t[r * 33 + k4] = v.x; a_t[r * 33 + k4 + 1] = v.y;
        a_t[r * 33 + k4 + 2] = v.z; a_t[r * 33 + k4 + 3] = v.w;
        float4 w = *(const float4*)&g_B[(h * NRES + j0 + r) * 32 + k4];
        b_t[r * 33 + k4] = w.x; b_t[r * 33 + k4 + 1] = w.y;
        b_t[r * 33 + k4 + 2] = w.z; b_t[r * 33 + k4 + 3] = w.w;
    }
    __syncthreads();
    int tx = tid & 15, ty = tid >> 4;
    float acc[4][4];
    #pragma unroll
    for (int r = 0; r < 4; r++)
        #pragma unroll
        for (int u = 0; u < 4; u++) acc[r][u] = 0.f;
    #pragma unroll 8
    for (int k = 0; k < 32; k++) {
        float av[4], bv[4];
        #pragma unroll
        for (int r = 0; r < 4; r++) av[r] = a_t[(ty * 4 + r) * 33 + k];
        #pragma unroll
        for (int u = 0; u < 4; u++) bv[u] = b_t[(tx * 4 + u) * 33 + k];
        #pragma unroll
        for (int r = 0; r < 4; r++)
            #pragma unroll
            for (int u = 0; u < 4; u++) acc[r][u] += av[r] * bv[u];
    }
    #pragma unroll
    for (int r = 0; r < 4; r++) {
        float4 o = make_float4(acc[r][0], acc[r][1], acc[r][2], acc[r][3]);
        *(float4*)&g_pre[((size_t)h * NRES + i0 + ty * 4 + r) * NRES + j0 + tx * 4] = o;
    }
}

// =============== K4: fused bias + logits + softmax + o_pair, per residue i ===============
// smem: zc[128*132]=16896  av2[512*12]=6144  wbT[12*128]=1536  -> 24576 floats = 98304 B
// (phase D reduction dred[12*512]=6144 overlays the zc region only)
// __launch_bounds__(512, 2): clamp regs to 64 so 2 CTAs co-reside (round-14 ran
// at 65 regs -> 1 CTA/SM -> occ 25% -> latency exposed; this is the fix).
__global__ __launch_bounds__(512, 2) void k_fused(const float* __restrict__ z,
                                                  const float* __restrict__ Wb,
                                                  const float* __restrict__ bb,
                                                  const float* __restrict__ mask) {
    extern __shared__ float sm[];
    float* zc  = sm;            // one 128-row j-chunk of z (132 stride pad)
    float* av2 = sm + 16896;    // [j][12]
    float* wbT = sm + 23040;    // [h][128]
    float* dred = sm;           // [h][jsub(4)][128] overlay (zc region, av2 untouched)
    int i = blockIdx.x;
    int tid = threadIdx.x;      // 512
    int lane = tid & 31, wid = tid >> 5;

    for (int idx = tid; idx < 1536; idx += 512) {
        int h = idx >> 7, k = idx & 127;
        wbT[idx] = Wb[k * 12 + h];
    }

    // ---- phase A: av2[j][h] = z[i,j,:] . Wb[:,h]  (chunk-gated; 4 warps/SMSP-balanced)
    int my_chunk = tid >> 7;
    int jloc_a = tid & 127;
    for (int chunk = 0; chunk < 4; chunk++) {
        __syncthreads();
        for (int f = tid; f < 4096; f += 512) {
            int r = f >> 5, c4 = (f & 31) << 2;
            *(float4*)&zc[r * 132 + c4] =
                *(const float4*)&z[((size_t)(i * NRES) + chunk * 128 + r) * CZ + c4];
        }
        __syncthreads();
        if (my_chunk == chunk) {
            unsigned long long acc2[12];
            #pragma unroll
            for (int h = 0; h < 12; h++) acc2[h] = 0ULL;
            #pragma unroll 4
            for (int c4 = 0; c4 < 32; c4++) {
                ulonglong2 zv = *(const ulonglong2*)&zc[jloc_a * 132 + c4 * 4];
                #pragma unroll
                for (int h = 0; h < 12; h++) {
                    ulonglong2 wv = *(const ulonglong2*)&wbT[h * 128 + c4 * 4];
                    fma2(acc2[h], zv.x, wv.x);
                    fma2(acc2[h], zv.y, wv.y);
                }
            }
            int j = chunk * 128 + jloc_a;
            #pragma unroll
            for (int h = 0; h < 12; h++) {
                float2 p = upk2(acc2[h]);
                av2[j * 12 + h] = p.x + p.y;
            }
        }
    }
    __syncthreads();

    // ---- phase B: full logits (exact mask term) ----
    {
        int j = tid;
        float mterm = 100000.0f * (mask[i] * mask[j] - 1.0f);
        const float C2 = 0.5773502691896258f;  // sqrt(1/3)
        #pragma unroll
        for (int h = 0; h < 12; h++) {
            float lg = g_pre[((size_t)h * NRES + i) * NRES + j] +
                       C2 * (av2[j * 12 + h] + bb[h]) + mterm;
            av2[j * 12 + h] = lg;
        }
    }
    __syncthreads();

    // ---- phase C: softmax, one warp per head ----
    if (wid < 12) {
        int h = wid;
        float vals[16];
        float m = -3.4e38f;
        #pragma unroll
        for (int u = 0; u < 16; u++) {
            vals[u] = av2[(u * 32 + lane) * 12 + h];
            m = fmaxf(m, vals[u]);
        }
        #pragma unroll
        for (int off = 16; off > 0; off >>= 1) m = fmaxf(m, __shfl_xor_sync(0xffffffffu, m, off));
        float s = 0.f;
        #pragma unroll
        for (int u = 0; u < 16; u++) { vals[u] = __expf(vals[u] - m); s += vals[u]; }
        #pragma unroll
        for (int off = 16; off > 0; off >>= 1) s += __shfl_xor_sync(0xffffffffu, s, off);
        float inv = 1.0f / s;
        #pragma unroll
        for (int u = 0; u < 16; u++) {
            float an = vals[u] * inv;
            av2[(u * 32 + lane) * 12 + h] = an;
            g_a[((size_t)h * NRES + i) * NRES + u * 32 + lane] = an;
        }
    }
    __syncthreads();

    // ---- phase D: o_pair[h][c] = sum_j a[j][h] * z[i,j,c]  (head-pair packing) ----
    // thread = (channel c = tid&127, jsub = tid>>7 -> 32 rows/chunk)
    // a loads are broadcast LDS.128 (pair-contiguous in h); only z needs dup2.
    int c = tid & 127;
    int jsub = tid >> 7;   // 0..3
    unsigned long long pacc[6];
    #pragma unroll
    for (int p = 0; p < 6; p++) pacc[p] = 0ULL;
    for (int chunk = 0; chunk < 4; chunk++) {
        __syncthreads();
        for (int f = tid; f < 4096; f += 512) {
            int r = f >> 5, c4 = (f & 31) << 2;
            *(float4*)&zc[r * 132 + c4] =
                *(const float4*)&z[((size_t)(i * NRES) + chunk * 128 + r) * CZ + c4];
        }
        __syncthreads();
        #pragma unroll 4
        for (int jj = 0; jj < 32; jj++) {
            int jloc = jsub * 32 + jj;
            int j = chunk * 128 + jloc;
            unsigned long long zs = dup2(zc[jloc * 132 + c]);
            ulonglong2 u0 = *(const ulonglong2*)&av2[j * 12];      // h 0-3
            ulonglong2 u1 = *(const ulonglong2*)&av2[j * 12 + 4];  // h 4-7
            ulonglong2 u2 = *(const ulonglong2*)&av2[j * 12 + 8];  // h 8-11
            fma2(pacc[0], zs, u0.x); fma2(pacc[1], zs, u0.y);
            fma2(pacc[2], zs, u1.x); fma2(pacc[3], zs, u1.y);
            fma2(pacc[4], zs, u2.x); fma2(pacc[5], zs, u2.y);
        }
    }
    // reduce 4 jsub partials per (h, channel): dred[h*512 + jsub*128 + c]
    __syncthreads();
    #pragma unroll
    for (int p = 0; p < 6; p++) {
        float2 pr = upk2(pacc[p]);
        dred[(2 * p + 0) * 512 + jsub * 128 + c] = pr.x;
        dred[(2 * p + 1) * 512 + jsub * 128 + c] = pr.y;
    }
    __syncthreads();
    #pragma unroll
    for (int r = 0; r < 3; r++) {
        int idx = tid + 512 * r;     // 0..1535
        int h = idx >> 7, cc = idx & 127;
        float ssum = 0.f;
        #pragma unroll
        for (int js = 0; js < 4; js++) ssum += dred[h * 512 + js * 128 + cc];
        g_cat[i * 2112 + 576 + h * 128 + cc] = ssum;
    }
}

// =============== K5: o + o_pt GEMM, j-split partials ===============
// grid (16 i-tiles of 32, 12 h, 2 j-splits), 320 threads
__global__ void k_ov() {
    extern __shared__ float sm[];
    float* a_t  = sm;          // 32 * 260
    float* v2_t = sm + 8320;   // 256 * 40
    int i0 = blockIdx.x * 32;
    int h = blockIdx.y;
    int j0 = blockIdx.z * 256;
    int tid = threadIdx.x;
    for (int f = tid; f < 2048; f += 320) {
        int r = f >> 6, j4 = (f & 63) << 2;
        *(float4*)&a_t[r * 260 + j4] =
            *(const float4*)&g_a[((size_t)h * NRES + i0 + r) * NRES + j0 + j4];
    }
    for (int f = tid; f < 2560; f += 320) {
        int jj = f / 10, c4 = (f % 10) << 2;
        *(float4*)&v2_t[jj * 40 + c4] = *(const float4*)&g_v2[(j0 + jj) * 480 + h * 40 + c4];
    }
    __syncthreads();
    int row = tid & 31, cg = tid >> 5;  // cg 0..9
    ulonglong2 acc2; acc2.x = 0ULL; acc2.y = 0ULL;
    #pragma unroll 4
    for (int j4 = 0; j4 < 64; j4++) {
        float4 a4 = *(const float4*)&a_t[row * 260 + j4 * 4];
        ulonglong2 v0 = *(const ulonglong2*)&v2_t[(j4 * 4 + 0) * 40 + cg * 4];
        ulonglong2 v1 = *(const ulonglong2*)&v2_t[(j4 * 4 + 1) * 40 + cg * 4];
        ulonglong2 v2 = *(const ulonglong2*)&v2_t[(j4 * 4 + 2) * 40 + cg * 4];
        ulonglong2 v3 = *(const ulonglong2*)&v2_t[(j4 * 4 + 3) * 40 + cg * 4];
        unsigned long long d0 = dup2(a4.x), d1 = dup2(a4.y), d2 = dup2(a4.z), d3 = dup2(a4.w);
        fma2(acc2.x, d0, v0.x); fma2(acc2.y, d0, v0.y);
        fma2(acc2.x, d1, v1.x); fma2(acc2.y, d1, v1.y);
        fma2(acc2.x, d2, v2.x); fma2(acc2.y, d2, v2.y);
        fma2(acc2.x, d3, v3.x); fma2(acc2.y, d3, v3.y);
    }
    float2 lo = upk2(acc2.x), hi = upk2(acc2.y);
    float4 o = make_float4(lo.x, lo.y, hi.x, hi.y);
    *(float4*)&g_ovp[((size_t)blockIdx.z * NRES + i0 + row) * 480 + h * 40 + cg * 4] = o;
}

// =============== K6: reduce j-split partials + inverse frame + norms ===============
__global__ void k_ovred(const float* __restrict__ rot, const float* __restrict__ trans) {
    int i = blockIdx.x;
    int tid = threadIdx.x;  // 192
    {
        int h = tid >> 4, c = tid & 15;
        float v = g_ovp[(size_t)i * 480 + h * 40 + c] +
                  g_ovp[(size_t)(NRES + i) * 480 + h * 40 + c];
        g_cat[i * 2112 + tid] = v;
    }
    if (tid < 96) {
        int h = tid >> 3, p = tid & 7;
        float s0 = g_ovp[(size_t)i * 480 + h * 40 + 16 + p * 3 + 0] +
                   g_ovp[(size_t)(NRES + i) * 480 + h * 40 + 16 + p * 3 + 0];
        float s1 = g_ovp[(size_t)i * 480 + h * 40 + 16 + p * 3 + 1] +
                   g_ovp[(size_t)(NRES + i) * 480 + h * 40 + 16 + p * 3 + 1];
        float s2 = g_ovp[(size_t)i * 480 + h * 40 + 16 + p * 3 + 2] +
                   g_ovp[(size_t)(NRES + i) * 480 + h * 40 + 16 + p * 3 + 2];
        float g0 = s0 - trans[i * 3 + 0];
        float g1 = s1 - trans[i * 3 + 1];
        float g2 = s2 - trans[i * 3 + 2];
        float lx = rot[i * 9 + 0] * g0 + rot[i * 9 + 3] * g1 + rot[i * 9 + 6] * g2;
        float ly = rot[i * 9 + 1] * g0 + rot[i * 9 + 4] * g1 + rot[i * 9 + 7] * g2;
        float lz = rot[i * 9 + 2] * g0 + rot[i * 9 + 5] * g1 + rot[i * 9 + 8] * g2;
        float nrm = sqrtf(lx * lx + ly * ly + lz * lz + 1e-8f);
        g_cat[i * 2112 + 192 + tid] = lx;
        g_cat[i * 2112 + 288 + tid] = ly;
        g_cat[i * 2112 + 384 + tid] = lz;
        g_cat[i * 2112 + 480 + tid] = nrm;
    }
}

// =============== K7: split-K output GEMM (64x48 tiles, 4x4 micro, f32x2) ===============
__global__ void k_out(const float* __restrict__ Wout) {
    __shared__ float cat_s[64 * 48];
    __shared__ float w_s[48 * 48];
    int tid = threadIdx.x;             // 192
    int tx = tid % 12, ty = tid / 12;
    int i0 = blockIdx.x * 64;
    int c0 = blockIdx.y * 48;
    int ks = blockIdx.z;
    ulonglong2 acc2[4];
    #pragma unroll
    for (int r = 0; r < 4; r++) { acc2[r].x = 0ULL; acc2[r].y = 0ULL; }

    for (int kc = 0; kc < 11; kc++) {
        int k0 = ks * 528 + kc * 48;
        __syncthreads();
        for (int f = tid; f < 768; f += 192) {
            int r = f / 12, c4 = (f % 12) << 2;
            *(float4*)&cat_s[r * 48 + c4] = *(const float4*)&g_cat[(i0 + r) * 2112 + k0 + c4];
        }
        for (int f = tid; f < 576; f += 192) {
            int r = f / 12, c4 = (f % 12) << 2;
            *(float4*)&w_s[r * 48 + c4] = *(const float4*)&Wout[(k0 + r) * 384 + c0 + c4];
        }
        __syncthreads();
        #pragma unroll 8
        for (int k = 0; k < 48; k++) {
            ulonglong2 wv = *(const ulonglong2*)&w_s[k * 48 + tx * 4];
            unsigned long long a0 = dup2(cat_s[(ty * 4 + 0) * 48 + k]);
            unsigned long long a1 = dup2(cat_s[(ty * 4 + 1) * 48 + k]);
            unsigned long long a2 = dup2(cat_s[(ty * 4 + 2) * 48 + k]);
            unsigned long long a3 = dup2(cat_s[(ty * 4 + 3) * 48 + k]);
            fma2(acc2[0].x, a0, wv.x); fma2(acc2[0].y, a0, wv.y);
            fma2(acc2[1].x, a1, wv.x); fma2(acc2[1].y, a1, wv.y);
            fma2(acc2[2].x, a2, wv.x); fma2(acc2[2].y, a2, wv.y);
            fma2(acc2[3].x, a3, wv.x); fma2(acc2[3].y, a3, wv.y);
        }
    }
    #pragma unroll
    for (int r = 0; r < 4; r++) {
        float2 lo = upk2(acc2[r].x), hi = upk2(acc2[r].y);
        float4 o = make_float4(lo.x, lo.y, hi.x, hi.y);
        *(float4*)&g_opart[((size_t)ks * NRES + i0 + ty * 4 + r) * 384 + c0 + tx * 4] = o;
    }
}

__global__ void k_out_red(const float* __restrict__ bout, float* __restrict__ out) {
    int f = blockIdx.x * 256 + threadIdx.x;  // 49152 float4 jobs
    int i = f / 96;
    int c4 = (f % 96) * 4;
    float4 s0 = *(const float4*)&g_opart[(size_t)0 * 196608 + i * 384 + c4];
    float4 s1 = *(const float4*)&g_opart[(size_t)1 * 196608 + i * 384 + c4];
    float4 s2 = *(const float4*)&g_opart[(size_t)2 * 196608 + i * 384 + c4];
    float4 s3 = *(const float4*)&g_opart[(size_t)3 * 196608 + i * 384 + c4];
    float4 bv = *(const float4*)&bout[c4];
    float4 o;
    o.x = s0.x + s1.x + s2.x + s3.x + bv.x;
    o.y = s0.y + s1.y + s2.y + s3.y + bv.y;
    o.z = s0.z + s1.z + s2.z + s3.z + bv.z;
    o.w = s0.w + s1.w + s2.w + s3.w + bv.w;
    *(float4*)&out[i * 384 + c4] = o;
}

extern "C" void kernel_launch(void* const* d_in, const int* in_sizes, int n_in,
                              void* d_out, int out_size) {
    const float* s     = (const float*)d_in[0];
    const float* z     = (const float*)d_in[1];
    const float* rot   = (const float*)d_in[2];
    const float* trans = (const float*)d_in[3];
    const float* mask  = (const float*)d_in[4];
    const float* Wq    = (const float*)d_in[5];
    const float* bq    = (const float*)d_in[6];
    const float* Wkv   = (const float*)d_in[7];
    const float* bkv   = (const float*)d_in[8];
    const float* Wqp   = (const float*)d_in[9];
    const float* bqp   = (const float*)d_in[10];
    const float* Wkvp  = (const float*)d_in[11];
    const float* bkvp  = (const float*)d_in[12];
    const float* Wb    = (const float*)d_in[13];
    const float* bb    = (const float*)d_in[14];
    const float* hwts  = (const float*)d_in[15];
    const float* Wout  = (const float*)d_in[16];
    const float* bout  = (const float*)d_in[17];
    float* out = (float*)d_out;

    const int FUSED_SMEM = 24576 * 4;   // 98304 B
    const int OV_SMEM    = 18560 * 4;   // 74240 B
    cudaFuncSetAttribute(k_fused, cudaFuncAttributeMaxDynamicSharedMemorySize, FUSED_SMEM);
    cudaFuncSetAttribute(k_ov, cudaFuncAttributeMaxDynamicSharedMemorySize, OV_SMEM);

    k_gemm_proj<<<dim3(8, 24), 192>>>(s, Wq, bq, Wkv, bkv, Wqp, bqp, Wkvp, bkvp);
    k_scatter<<<NRES, 192>>>(rot, trans, hwts);
    k_pre<<<dim3(8, 8, 12), 256>>>();
    k_fused<<<NRES, 512, FUSED_SMEM>>>(z, Wb, bb, mask);
    k_ov<<<dim3(16, 12, 2), 320, OV_SMEM>>>();
    k_ovred<<<NRES, 192>>>(rot, trans);
    k_out<<<dim3(8, 8, 4), 192>>>(Wout);
    k_out_red<<<192, 256>>>(bout, out);
}